// round 11
// baseline (speedup 1.0000x reference)
#include <cuda_runtime.h>
#include <cuda_fp16.h>
#include <math.h>
#include <stdint.h>

#define NB 512
#define NCTA 256   // 2 samples per CTA -> single wave on 148 SMs x 2 CTAs
#define NF 64
#define NK 64
#define US 80      // u32 row stride (floats)
#define UHS 88     // u16/w1h row stride (halves); 88 halves = 11 uint4
#define SVS 68     // sv row stride (floats)

typedef unsigned long long ull;

// upper-triangular 8x8 tile enumeration (36 tiles)
__device__ __constant__ unsigned char TI_ARR[36] = {
    0,0,0,0,0,0,0,0,
    1,1,1,1,1,1,1,
    2,2,2,2,2,2,
    3,3,3,3,3,
    4,4,4,4,
    5,5,5,
    6,6,
    7};
__device__ __constant__ unsigned char TJ_ARR[36] = {
    0,1,2,3,4,5,6,7,
    1,2,3,4,5,6,7,
    2,3,4,5,6,7,
    3,4,5,6,7,
    4,5,6,7,
    5,6,7,
    6,7,
    7};

__device__ __forceinline__ uint32_t to_tf32(float f) {
    uint32_t r;
    asm("cvt.rna.tf32.f32 %0, %1;" : "=r"(r) : "f"(f));
    return r;
}
__device__ __forceinline__ uint32_t hmul2(uint32_t a, uint32_t b) {
    uint32_t d;
    asm("mul.rn.f16x2 %0, %1, %2;" : "=r"(d) : "r"(a), "r"(b));
    return d;
}
__device__ __forceinline__ uint32_t packh2(float lo, float hi) {
    uint32_t d;
    asm("cvt.rn.f16x2.f32 %0, %1, %2;" : "=r"(d) : "f"(hi), "f"(lo));
    return d;
}
__device__ __forceinline__ uint32_t packh2_relu(float lo, float hi) {
    uint32_t d;
    asm("cvt.rn.relu.f16x2.f32 %0, %1, %2;" : "=r"(d) : "f"(hi), "f"(lo));
    return d;
}

// D[16x8] += A[16x16](f16) * B[16x8](f16 col-major), f32 accum
__device__ __forceinline__ void mma16(float c[4],
                                      uint32_t a0, uint32_t a1,
                                      uint32_t a2, uint32_t a3,
                                      uint32_t b0, uint32_t b1) {
    asm("mma.sync.aligned.m16n8k16.row.col.f32.f16.f16.f32 "
        "{%0,%1,%2,%3}, {%4,%5,%6,%7}, {%8,%9}, {%0,%1,%2,%3};"
        : "+f"(c[0]), "+f"(c[1]), "+f"(c[2]), "+f"(c[3])
        : "r"(a0), "r"(a1), "r"(a2), "r"(a3), "r"(b0), "r"(b1));
}
// D[16x8] += A[16x8](tf32) * B[8x8](tf32 col-major)  (pass 3)
__device__ __forceinline__ void mma8(float c[4],
                                     uint32_t a0, uint32_t a1,
                                     uint32_t a2, uint32_t a3,
                                     uint32_t b0, uint32_t b1) {
    asm("mma.sync.aligned.m16n8k8.row.col.f32.tf32.tf32.f32 "
        "{%0,%1,%2,%3}, {%4,%5,%6,%7}, {%8,%9}, {%0,%1,%2,%3};"
        : "+f"(c[0]), "+f"(c[1]), "+f"(c[2]), "+f"(c[3])
        : "r"(a0), "r"(a1), "r"(a2), "r"(a3), "r"(b0), "r"(b1));
}

// f32 fragment position (pass 3): k -> 16*(k>>4) + 4*(k&3) + ((k>>2)&3)
__device__ __forceinline__ int posk(int k) {
    return ((k >> 4) << 4) | ((k & 3) << 2) | ((k >> 2) & 3);
}

// dynamic smem (floats)
#define OFF_U32 0                       // 5120
#define OFF_U16 5120                    // 2816
#define OFF_W1H 7936                    // 2816
#define OFF_SV0 10752                   // 4352
#define OFF_SV1 15104                   // 4352
#define OFF_WD1 19456                   // 2048
#define OFF_WD2 21504                   // 672
#define OFF_WD3 22176                   // 336
#define OFF_WO  22512                   // 16
#define OFF_WW  22528                   // 64
#define OFF_BDS 22592                   // 80: bd1@0, bd2@32, bd3@56, bo@72, bw@73
#define DSM_FLOATS 22672                // 90,688 B

__global__ void __launch_bounds__(256, 2)
afm_kernel(const float* __restrict__ x,
           const float* __restrict__ Ww,  const float* __restrict__ bw,
           const float* __restrict__ cross,
           const float* __restrict__ W1,  const float* __restrict__ b1,
           const float* __restrict__ w2,
           const float* __restrict__ Wd1, const float* __restrict__ bd1,
           const float* __restrict__ Wd2, const float* __restrict__ bd2,
           const float* __restrict__ Wd3, const float* __restrict__ bd3,
           const float* __restrict__ Wo,  const float* __restrict__ bo,
           float* __restrict__ out)
{
    extern __shared__ float dsm[];
    float*   u    = dsm + OFF_U32;
    __half*  u16p = (__half*)(dsm + OFF_U16);
    __half*  w1p  = (__half*)(dsm + OFF_W1H);
    float*   sv0  = dsm + OFF_SV0;
    float*   sv1  = dsm + OFF_SV1;
    float*   wd1s = dsm + OFF_WD1;
    float*   wd2s = dsm + OFF_WD2;
    float*   wd3s = dsm + OFF_WD3;
    float*   wos  = dsm + OFF_WO;
    float*   wws  = dsm + OFF_WW;
    float*   bds  = dsm + OFF_BDS;

    __shared__ float xb2[2][NF], b1s[NK], w2s[NK];
    __shared__ float redbuf[16];           // [0..8) warp maxes, [8..16) warp sums
    __shared__ float acc4s[4][NK];
    __shared__ float tmpv2[2][NK];
    __shared__ float d1s[2][32], d2s[2][24], d3s[2][16];

    const int b0   = blockIdx.x << 1;
    const int tid  = threadIdx.x;
    const int wid  = tid >> 5;
    const int lane = tid & 31;
    const int grp  = lane >> 2;     // 0..7
    const int qc   = lane & 3;      // 0..3

    if (tid < 128) xb2[tid >> 6][tid & 63] = x[b0 * NF + tid];
    if (tid < NF) {
        b1s[tid] = b1[tid];
        w2s[tid] = w2[tid];
    }

    // ---- sample-invariant staging (ONCE): W1h fp16, deep weights, biases ----
    {
        const float4* W14 = (const float4*)W1;
        __half2* w1h2 = (__half2*)w1p;
        for (int q4 = tid; q4 < NF * 16; q4 += 256) {
            const int r  = q4 >> 4;
            const int c4 = q4 & 15;
            // fp16 chunk layout: half idx = r*88 + 16*qc + 4*s + 2*e + d
            const int h2base = (r * UHS + (((c4 & 1) << 1) << 4)
                                + ((c4 >> 2) << 2) + (((c4 >> 1) & 1) << 1)) >> 1;
            const float4 w4 = W14[q4];
            w1h2[h2base]     = __floats2half2_rn(w4.x, w4.y);
            w1h2[h2base + 8] = __floats2half2_rn(w4.z, w4.w);
        }
        const float4* Wd14 = (const float4*)Wd1;
        float4* wd1s4 = (float4*)wd1s;
        for (int i = tid; i < 512; i += 256) wd1s4[i] = Wd14[i];
        if (tid < 168) ((float4*)wd2s)[tid] = ((const float4*)Wd2)[tid];
        if (tid < 84)  ((float4*)wd3s)[tid] = ((const float4*)Wd3)[tid];
        if (tid < 4)   ((float4*)wos)[tid]  = ((const float4*)Wo)[tid];
        if (tid < 16)  ((float4*)wws)[tid]  = ((const float4*)Ww)[tid];
        if (tid < 32)  bds[tid]      = bd1[tid];
        if (tid < 21)  bds[32 + tid] = bd2[tid];
        if (tid < 16)  bds[56 + tid] = bd3[tid];
        if (tid == 0) { bds[72] = bo[0]; bds[73] = bw[0]; }
    }
    __syncthreads();

    // hoisted per-warp fragments (live across both samples)
    const int nh = wid & 1;
    const int wp = wid >> 1;        // 0..3

    uint2 Bc[4][4];
    #pragma unroll
    for (int nt = 0; nt < 4; nt++) {
        const uint4* wr4 = (const uint4*)(w1p + ((nh * 4 + nt) * 8 + grp) * UHS);
        const uint4 v0 = wr4[2 * qc];
        const uint4 v1 = wr4[2 * qc + 1];
        Bc[nt][0] = make_uint2(v0.x, v0.y);
        Bc[nt][1] = make_uint2(v0.z, v0.w);
        Bc[nt][2] = make_uint2(v1.x, v1.y);
        Bc[nt][3] = make_uint2(v1.z, v1.w);
    }
    uint32_t w2f[2][2];
    #pragma unroll
    for (int s = 0; s < 2; s++) {
        const int base = nh * 32 + 16 * s;
        w2f[s][0] = packh2(w2s[base + 2 * qc],     w2s[base + 2 * qc + 1]);
        w2f[s][1] = packh2(w2s[base + 8 + 2 * qc], w2s[base + 8 + 2 * qc + 1]);
    }
    float2 b1f[4];
    #pragma unroll
    for (int nt = 0; nt < 4; nt++) {
        b1f[nt].x = b1s[nh * 32 + nt * 8 + 2 * qc];
        b1f[nt].y = b1s[nh * 32 + nt * 8 + 2 * qc + 1];
    }
    float* svp = nh ? sv1 : sv0;

    // ======================= per-sample loop =======================
    for (int smp = 0; smp < 2; smp++) {
        const float* xbs = xb2[smp];

        // ---- per-sample staging: u32 (posk) + u16 (chunk layout) ----
        {
            const float4* cr4 = (const float4*)cross;
            __half2* u16h = (__half2*)u16p;
            for (int q4 = tid; q4 < NF * 16; q4 += 256) {
                const int r  = q4 >> 4;
                const int c4 = q4 & 15;
                const float sc = xbs[r];
                const float4 cc = cr4[q4];
                float4 uu;
                uu.x = sc*cc.x; uu.y = sc*cc.y; uu.z = sc*cc.z; uu.w = sc*cc.w;
                const int kb = c4 << 2;
                const int b32 = r * US + ((kb >> 4) << 4) + ((kb >> 2) & 3);
                u[b32 + 0]  = uu.x;
                u[b32 + 4]  = uu.y;
                u[b32 + 8]  = uu.z;
                u[b32 + 12] = uu.w;
                const int h2base = (r * UHS + (((c4 & 1) << 1) << 4)
                                    + ((c4 >> 2) << 2)
                                    + (((c4 >> 1) & 1) << 1)) >> 1;
                u16h[h2base]     = __floats2half2_rn(uu.x, uu.y);
                u16h[h2base + 8] = __floats2half2_rn(uu.z, uu.w);
            }
        }
        __syncthreads();

        // ---------------- Pass 1: fp16 mma.sync scores ----------------
        float wmax = -3.4e38f;
        for (int p = wp; p < 72; p += 4) {
            const int t  = p >> 1;
            const int h  = p & 1;
            const int ib = TI_ARR[t] * 8 + 4 * h;
            const int jb = TJ_ARR[t] * 8;
            const uint4* uj4 = (const uint4*)(u16p + (jb + grp) * UHS);
            const uint4* ua4 = (const uint4*)(u16p + ib * UHS);

            float acc0[4][4], acc1[4][4];
            #pragma unroll
            for (int nt = 0; nt < 4; nt++) {
                acc0[nt][0] = b1f[nt].x; acc0[nt][1] = b1f[nt].y;
                acc0[nt][2] = b1f[nt].x; acc0[nt][3] = b1f[nt].y;
                acc1[nt][0] = b1f[nt].x; acc1[nt][1] = b1f[nt].y;
                acc1[nt][2] = b1f[nt].x; acc1[nt][3] = b1f[nt].y;
            }

            #pragma unroll
            for (int c = 0; c < 2; c++) {
                const int o = 2 * qc + c;
                const uint4 uj = uj4[o];
                const uint4 q0 = ua4[o];
                const uint4 q1 = ua4[o + 11];
                const uint4 q2 = ua4[o + 22];
                const uint4 q3 = ua4[o + 33];
                {
                    const uint32_t a0 = hmul2(q0.x, uj.x);
                    const uint32_t a1 = hmul2(q1.x, uj.x);
                    const uint32_t a2 = hmul2(q0.y, uj.y);
                    const uint32_t a3 = hmul2(q1.y, uj.y);
                    const uint32_t c0 = hmul2(q2.x, uj.x);
                    const uint32_t c1 = hmul2(q3.x, uj.x);
                    const uint32_t c2 = hmul2(q2.y, uj.y);
                    const uint32_t c3 = hmul2(q3.y, uj.y);
                    #pragma unroll
                    for (int nt = 0; nt < 4; nt++) {
                        mma16(acc0[nt], a0, a1, a2, a3,
                              Bc[nt][2 * c].x, Bc[nt][2 * c].y);
                        mma16(acc1[nt], c0, c1, c2, c3,
                              Bc[nt][2 * c].x, Bc[nt][2 * c].y);
                    }
                }
                {
                    const uint32_t a0 = hmul2(q0.z, uj.z);
                    const uint32_t a1 = hmul2(q1.z, uj.z);
                    const uint32_t a2 = hmul2(q0.w, uj.w);
                    const uint32_t a3 = hmul2(q1.w, uj.w);
                    const uint32_t c0 = hmul2(q2.z, uj.z);
                    const uint32_t c1 = hmul2(q3.z, uj.z);
                    const uint32_t c2 = hmul2(q2.w, uj.w);
                    const uint32_t c3 = hmul2(q3.w, uj.w);
                    #pragma unroll
                    for (int nt = 0; nt < 4; nt++) {
                        mma16(acc0[nt], a0, a1, a2, a3,
                              Bc[nt][2 * c + 1].x, Bc[nt][2 * c + 1].y);
                        mma16(acc1[nt], c0, c1, c2, c3,
                              Bc[nt][2 * c + 1].x, Bc[nt][2 * c + 1].y);
                    }
                }
            }

            // tensor-core epilogue: s = relu(H) . w2
            float s0[4] = {0.f, 0.f, 0.f, 0.f};
            mma16(s0,
                  packh2_relu(acc0[0][0], acc0[0][1]),
                  packh2_relu(acc0[0][2], acc0[0][3]),
                  packh2_relu(acc0[1][0], acc0[1][1]),
                  packh2_relu(acc0[1][2], acc0[1][3]),
                  w2f[0][0], w2f[0][1]);
            mma16(s0,
                  packh2_relu(acc0[2][0], acc0[2][1]),
                  packh2_relu(acc0[2][2], acc0[2][3]),
                  packh2_relu(acc0[3][0], acc0[3][1]),
                  packh2_relu(acc0[3][2], acc0[3][3]),
                  w2f[1][0], w2f[1][1]);
            float s1[4] = {0.f, 0.f, 0.f, 0.f};
            mma16(s1,
                  packh2_relu(acc1[0][0], acc1[0][1]),
                  packh2_relu(acc1[0][2], acc1[0][3]),
                  packh2_relu(acc1[1][0], acc1[1][1]),
                  packh2_relu(acc1[1][2], acc1[1][3]),
                  w2f[0][0], w2f[0][1]);
            mma16(s1,
                  packh2_relu(acc1[2][0], acc1[2][1]),
                  packh2_relu(acc1[2][2], acc1[2][3]),
                  packh2_relu(acc1[3][0], acc1[3][1]),
                  packh2_relu(acc1[3][2], acc1[3][3]),
                  w2f[1][0], w2f[1][1]);

            wmax = fmaxf(wmax, fmaxf(fmaxf(s0[0], s0[2]), fmaxf(s1[0], s1[2])));

            if (qc == 0) {
                const int j = jb + grp;
                svp[(ib + 0) * SVS + j] = s0[0];
                svp[(ib + 1) * SVS + j] = s0[2];
                svp[(ib + 2) * SVS + j] = s1[0];
                svp[(ib + 3) * SVS + j] = s1[2];
            }
        }
        #pragma unroll
        for (int d = 16; d; d >>= 1)
            wmax = fmaxf(wmax, __shfl_xor_sync(~0u, wmax, d));
        if (lane == 0) redbuf[wid] = wmax;
        __syncthreads();

        // m = max(0, maxP0 + maxP1) >= true max (valid shift, exact math)
        const float mP0 = fmaxf(fmaxf(redbuf[0], redbuf[2]),
                                fmaxf(redbuf[4], redbuf[6]));
        const float mP1 = fmaxf(fmaxf(redbuf[1], redbuf[3]),
                                fmaxf(redbuf[5], redbuf[7]));
        const float m = fmaxf(0.f, mP0 + mP1);

        // ---------------- Pass 2: masked softmax ----------------
        float le = 0.f;
        #pragma unroll
        for (int it = 0; it < 16; it++) {
            const int lin = tid + it * 256;
            const int i = lin >> 6, j = lin & 63;
            const int sidx = i * SVS + j;
            const bool valid = (j >= i) && (xbs[i] != 0.f) && (xbs[j] != 0.f);
            const float s = sv0[sidx] + sv1[sidx];
            float e = valid ? __expf(s - m) : 0.f;
            e = __uint_as_float(to_tf32(e));
            sv0[sidx] = e;
            le += e;
        }
        #pragma unroll
        for (int d = 16; d; d >>= 1) le += __shfl_xor_sync(~0u, le, d);
        if (lane == 0) redbuf[8 + wid] = le;
        __syncthreads();

        // ---- Pass 3: V = E @ U (tf32); tmp[k] = sum_i u[i,k] V[i,k] ----
        {
            const int mt    = wid >> 1;
            const int nbase = (wid & 1) * 4;

            float vacc[4][4];
            #pragma unroll
            for (int cc = 0; cc < 4; cc++)
                #pragma unroll
                for (int q = 0; q < 4; q++) vacc[cc][q] = 0.f;

            int pkb[4];
            #pragma unroll
            for (int cc = 0; cc < 4; cc++)
                pkb[cc] = posk(8 * (nbase + cc) + grp);

            const float* e0 = sv0 + (16 * mt + grp) * SVS;
            const float* e1 = sv0 + (16 * mt + grp + 8) * SVS;

            #pragma unroll
            for (int js = 0; js < 8; js++) {
                const int jc = 8 * js + qc;
                const uint32_t a0 = __float_as_uint(e0[jc]);
                const uint32_t a1 = __float_as_uint(e1[jc]);
                const uint32_t a2 = __float_as_uint(e0[jc + 4]);
                const uint32_t a3 = __float_as_uint(e1[jc + 4]);
                const float* uj0 = u + jc * US;
                const float* uj1 = u + (jc + 4) * US;
                #pragma unroll
                for (int cc = 0; cc < 4; cc++) {
                    const uint32_t b0v = __float_as_uint(uj0[pkb[cc]]);
                    const uint32_t b1v = __float_as_uint(uj1[pkb[cc]]);
                    mma8(vacc[cc], a0, a1, a2, a3, b0v, b1v);
                }
            }

            float part[8];
            #pragma unroll
            for (int cc = 0; cc < 4; cc++) {
                const int k0 = 8 * (nbase + cc) + 2 * qc;
                const int i0 = 16 * mt + grp;
                const float u00 = u[i0 * US + posk(k0)];
                const float u01 = u[i0 * US + posk(k0 + 1)];
                const float u10 = u[(i0 + 8) * US + posk(k0)];
                const float u11 = u[(i0 + 8) * US + posk(k0 + 1)];
                part[2 * cc]     = fmaf(vacc[cc][0], u00, vacc[cc][2] * u10);
                part[2 * cc + 1] = fmaf(vacc[cc][1], u01, vacc[cc][3] * u11);
            }
            #pragma unroll
            for (int d = 4; d <= 16; d <<= 1)
                #pragma unroll
                for (int q = 0; q < 8; q++)
                    part[q] += __shfl_xor_sync(0xffffffffu, part[q], d);

            if (grp == 0) {
                #pragma unroll
                for (int cc = 0; cc < 4; cc++) {
                    const int k0 = 8 * (nbase + cc) + 2 * qc;
                    acc4s[mt][k0]     = part[2 * cc];
                    acc4s[mt][k0 + 1] = part[2 * cc + 1];
                }
            }
        }
        __syncthreads();
        if (tid < NK) {
            float denom = __expf(-m);
            #pragma unroll
            for (int w = 0; w < 8; w++) denom += redbuf[8 + w];
            tmpv2[smp][tid] = (acc4s[0][tid] + acc4s[1][tid] +
                               acc4s[2][tid] + acc4s[3][tid]) / denom;
        }
        // next-iteration staging writes (u/u16) are disjoint from
        // acc4s/redbuf/tmpv2 reads above; the post-staging sync orders all.
    }
    __syncthreads();

    // ---------------- Pass 4: deep MLP, warp w = sample w ----------------
    if (wid < 2) {
        const int s = wid;
        {
            float a = bds[lane];                       // bd1
            const float4* w4 = (const float4*)(wd1s + lane * 64);
            #pragma unroll 4
            for (int j4 = 0; j4 < 16; j4++) {
                const float4 wv = w4[j4];
                a = fmaf(wv.x, tmpv2[s][4 * j4 + 0], a);
                a = fmaf(wv.y, tmpv2[s][4 * j4 + 1], a);
                a = fmaf(wv.z, tmpv2[s][4 * j4 + 2], a);
                a = fmaf(wv.w, tmpv2[s][4 * j4 + 3], a);
            }
            d1s[s][lane] = fmaxf(a, 0.f);
        }
        __syncwarp();
        if (lane < 21) {
            float a = bds[32 + lane];                  // bd2
            const float4* w4 = (const float4*)(wd2s + lane * 32);
            #pragma unroll
            for (int j4 = 0; j4 < 8; j4++) {
                const float4 wv = w4[j4];
                a = fmaf(wv.x, d1s[s][4 * j4 + 0], a);
                a = fmaf(wv.y, d1s[s][4 * j4 + 1], a);
                a = fmaf(wv.z, d1s[s][4 * j4 + 2], a);
                a = fmaf(wv.w, d1s[s][4 * j4 + 3], a);
            }
            d2s[s][lane] = fmaxf(a, 0.f);
        }
        __syncwarp();
        if (lane < 16) {
            float a = bds[56 + lane];                  // bd3
            const float* w = wd3s + lane * 21;
            #pragma unroll
            for (int j = 0; j < 21; j++) a = fmaf(w[j], d2s[s][j], a);
            d3s[s][lane] = fmaxf(a, 0.f);
        }
        __syncwarp();
        if (lane == 0) {
            float o = bds[72];                         // bo
            #pragma unroll
            for (int j = 0; j < 16; j++) o = fmaf(wos[j], d3s[s][j], o);
            float lin = bds[73];                       // bw
            #pragma unroll 8
            for (int f = 0; f < NF; f++) lin = fmaf(wws[f], xb2[s][f], lin);
            out[b0 + s] = 1.f / (1.f + __expf(-(lin + o)));
        }
    }
}

extern "C" void kernel_launch(void* const* d_in, const int* in_sizes, int n_in,
                              void* d_out, int out_size)
{
    const float* x     = (const float*)d_in[0];
    const float* Ww    = (const float*)d_in[1];
    const float* bw    = (const float*)d_in[2];
    const float* cross = (const float*)d_in[3];
    const float* W1    = (const float*)d_in[4];
    const float* b1    = (const float*)d_in[5];
    const float* w2    = (const float*)d_in[6];
    const float* Wd1   = (const float*)d_in[7];
    const float* bd1   = (const float*)d_in[8];
    const float* Wd2   = (const float*)d_in[9];
    const float* bd2   = (const float*)d_in[10];
    const float* Wd3   = (const float*)d_in[11];
    const float* bd3   = (const float*)d_in[12];
    const float* Wo    = (const float*)d_in[13];
    const float* bo    = (const float*)d_in[14];
    float* out = (float*)d_out;

    const size_t dyn_smem = (size_t)DSM_FLOATS * sizeof(float); // 90,688 B
    cudaFuncSetAttribute(afm_kernel,
                         cudaFuncAttributeMaxDynamicSharedMemorySize,
                         (int)dyn_smem);

    afm_kernel<<<NCTA, 256, dyn_smem>>>(x, Ww, bw, cross, W1, b1, w2,
                                        Wd1, bd1, Wd2, bd2, Wd3, bd3, Wo, bo,
                                        out);
}

// round 12
// speedup vs baseline: 1.0796x; 1.0796x over previous
#include <cuda_runtime.h>
#include <cuda_fp16.h>
#include <math.h>
#include <stdint.h>

#define NB 512
#define NF 64
#define NK 64
#define US 80      // u32 row stride (floats)
#define UHS 88     // u16/w1h row stride (halves); 88 halves = 11 uint4
#define SVS 68     // sv row stride (floats)

typedef unsigned long long ull;

// upper-triangular 8x8 tile enumeration (36 tiles)
__device__ __constant__ unsigned char TI_ARR[36] = {
    0,0,0,0,0,0,0,0,
    1,1,1,1,1,1,1,
    2,2,2,2,2,2,
    3,3,3,3,3,
    4,4,4,4,
    5,5,5,
    6,6,
    7};
__device__ __constant__ unsigned char TJ_ARR[36] = {
    0,1,2,3,4,5,6,7,
    1,2,3,4,5,6,7,
    2,3,4,5,6,7,
    3,4,5,6,7,
    4,5,6,7,
    5,6,7,
    6,7,
    7};

__device__ __forceinline__ uint32_t to_tf32(float f) {
    uint32_t r;
    asm("cvt.rna.tf32.f32 %0, %1;" : "=r"(r) : "f"(f));
    return r;
}
__device__ __forceinline__ uint32_t hmul2(uint32_t a, uint32_t b) {
    uint32_t d;
    asm("mul.rn.f16x2 %0, %1, %2;" : "=r"(d) : "r"(a), "r"(b));
    return d;
}
__device__ __forceinline__ uint32_t packh2(float lo, float hi) {
    uint32_t d;
    asm("cvt.rn.f16x2.f32 %0, %1, %2;" : "=r"(d) : "f"(hi), "f"(lo));
    return d;
}
__device__ __forceinline__ uint32_t packh2_relu(float lo, float hi) {
    uint32_t d;
    asm("cvt.rn.relu.f16x2.f32 %0, %1, %2;" : "=r"(d) : "f"(hi), "f"(lo));
    return d;
}

// D[16x8] += A[16x16](f16) * B[16x8](f16 col-major), f32 accum
__device__ __forceinline__ void mma16(float c[4],
                                      uint32_t a0, uint32_t a1,
                                      uint32_t a2, uint32_t a3,
                                      uint32_t b0, uint32_t b1) {
    asm("mma.sync.aligned.m16n8k16.row.col.f32.f16.f16.f32 "
        "{%0,%1,%2,%3}, {%4,%5,%6,%7}, {%8,%9}, {%0,%1,%2,%3};"
        : "+f"(c[0]), "+f"(c[1]), "+f"(c[2]), "+f"(c[3])
        : "r"(a0), "r"(a1), "r"(a2), "r"(a3), "r"(b0), "r"(b1));
}
// D[16x8] += A[16x8](tf32) * B[8x8](tf32 col-major)  (pass 3)
__device__ __forceinline__ void mma8(float c[4],
                                     uint32_t a0, uint32_t a1,
                                     uint32_t a2, uint32_t a3,
                                     uint32_t b0, uint32_t b1) {
    asm("mma.sync.aligned.m16n8k8.row.col.f32.tf32.tf32.f32 "
        "{%0,%1,%2,%3}, {%4,%5,%6,%7}, {%8,%9}, {%0,%1,%2,%3};"
        : "+f"(c[0]), "+f"(c[1]), "+f"(c[2]), "+f"(c[3])
        : "r"(a0), "r"(a1), "r"(a2), "r"(a3), "r"(b0), "r"(b1));
}

// f32 fragment position (pass 3): k -> 16*(k>>4) + 4*(k&3) + ((k>>2)&3)
__device__ __forceinline__ int posk(int k) {
    return ((k >> 4) << 4) | ((k & 3) << 2) | ((k >> 2) & 3);
}

// dynamic smem (floats)
#define OFF_U32 0                       // 5120
#define OFF_U16 5120                    // 64*88 halves = 2816 floats
#define OFF_W1H 7936                    // 2816
#define OFF_SV0 10752                   // 4352
#define OFF_SV1 15104                   // 4352
#define OFF_WD1 19456                   // 2048
#define OFF_WD2 21504                   // 672
#define OFF_WD3 22176                   // 336
#define OFF_WO  22512                   // 16
#define OFF_WW  22528                   // 64
#define DSM_FLOATS 22592                // 90368 B

__global__ void __launch_bounds__(256, 2)
afm_kernel(const float* __restrict__ x,
           const float* __restrict__ Ww,  const float* __restrict__ bw,
           const float* __restrict__ cross,
           const float* __restrict__ W1,  const float* __restrict__ b1,
           const float* __restrict__ w2,
           const float* __restrict__ Wd1, const float* __restrict__ bd1,
           const float* __restrict__ Wd2, const float* __restrict__ bd2,
           const float* __restrict__ Wd3, const float* __restrict__ bd3,
           const float* __restrict__ Wo,  const float* __restrict__ bo,
           float* __restrict__ out)
{
    extern __shared__ float dsm[];
    float*   u    = dsm + OFF_U32;
    __half*  u16p = (__half*)(dsm + OFF_U16);
    __half*  w1p  = (__half*)(dsm + OFF_W1H);
    float*   sv0  = dsm + OFF_SV0;
    float*   sv1  = dsm + OFF_SV1;
    float*   wd1s = dsm + OFF_WD1;
    float*   wd2s = dsm + OFF_WD2;
    float*   wd3s = dsm + OFF_WD3;
    float*   wos  = dsm + OFF_WO;
    float*   wws  = dsm + OFF_WW;

    __shared__ __align__(16) float xb[NF];
    __shared__ float b1s[NK], w2s[NK];
    __shared__ float redbuf[16];           // [0..8) warp maxes, [8..16) warp sums
    __shared__ float acc4s[4][NK];
    __shared__ float tmpv[NK];
    __shared__ float d1s[32], d2s[24], d3s[16];

    const int b    = blockIdx.x;
    const int tid  = threadIdx.x;
    const int wid  = tid >> 5;
    const int lane = tid & 31;
    const int grp  = lane >> 2;     // 0..7
    const int qc   = lane & 3;      // 0..3

    if (tid < NF) {
        xb[tid]  = x[b * NF + tid];
        b1s[tid] = b1[tid];
        w2s[tid] = w2[tid];
    }
    __syncthreads();

    // ---- staging: u32 (posk layout), u16/W1h ((qc,s)-chunk layout),
    //      plus deep-MLP weights into smem ----
    {
        const float4* cr4 = (const float4*)cross;
        const float4* W14 = (const float4*)W1;
        __half2* u16h = (__half2*)u16p;
        __half2* w1h2 = (__half2*)w1p;
        for (int q4 = tid; q4 < NF * 16; q4 += 256) {
            const int r  = q4 >> 4;
            const int c4 = q4 & 15;
            const float s = xb[r];
            const float4 cc = cr4[q4];
            float4 uu;
            uu.x = s*cc.x; uu.y = s*cc.y; uu.z = s*cc.z; uu.w = s*cc.w;
            // u32: posk layout, row stride 80 floats
            const int kb = c4 << 2;
            const int b32 = r * US + ((kb >> 4) << 4) + ((kb >> 2) & 3);
            u[b32 + 0]  = uu.x;
            u[b32 + 4]  = uu.y;
            u[b32 + 8]  = uu.z;
            u[b32 + 12] = uu.w;
            // fp16 chunk layout: half idx = r*88 + 16*qc + 4*s + 2*e + d
            const int h2base = (r * UHS + (((c4 & 1) << 1) << 4)
                                + ((c4 >> 2) << 2) + (((c4 >> 1) & 1) << 1)) >> 1;
            u16h[h2base]     = __floats2half2_rn(uu.x, uu.y);
            u16h[h2base + 8] = __floats2half2_rn(uu.z, uu.w);
            const float4 w4 = W14[q4];
            w1h2[h2base]     = __floats2half2_rn(w4.x, w4.y);
            w1h2[h2base + 8] = __floats2half2_rn(w4.z, w4.w);
        }
        // deep weights -> smem (overlaps with LDG latency above)
        const float4* Wd14 = (const float4*)Wd1;
        float4* wd1s4 = (float4*)wd1s;
        for (int i = tid; i < 512; i += 256) wd1s4[i] = Wd14[i];
        if (tid < 168) ((float4*)wd2s)[tid] = ((const float4*)Wd2)[tid];
        if (tid < 84)  ((float4*)wd3s)[tid] = ((const float4*)Wd3)[tid];
        if (tid < 4)   ((float4*)wos)[tid]  = ((const float4*)Wo)[tid];
        if (tid < 16)  ((float4*)wws)[tid]  = ((const float4*)Ww)[tid];
    }
    __syncthreads();

    // ---------------- Pass 1: attention scores via fp16 mma.sync -----------
    const int nh = wid & 1;
    const int wp = wid >> 1;        // 0..3

    uint2 Bc[4][4];                 // [nt][k16-step]
    #pragma unroll
    for (int nt = 0; nt < 4; nt++) {
        const uint4* wr4 = (const uint4*)(w1p + ((nh * 4 + nt) * 8 + grp) * UHS);
        const uint4 v0 = wr4[2 * qc];
        const uint4 v1 = wr4[2 * qc + 1];
        Bc[nt][0] = make_uint2(v0.x, v0.y);
        Bc[nt][1] = make_uint2(v0.z, v0.w);
        Bc[nt][2] = make_uint2(v1.x, v1.y);
        Bc[nt][3] = make_uint2(v1.z, v1.w);
    }
    uint32_t w2f[2][2];
    #pragma unroll
    for (int s = 0; s < 2; s++) {
        const int base = nh * 32 + 16 * s;
        w2f[s][0] = packh2(w2s[base + 2 * qc],     w2s[base + 2 * qc + 1]);
        w2f[s][1] = packh2(w2s[base + 8 + 2 * qc], w2s[base + 8 + 2 * qc + 1]);
    }
    float2 b1f[4];
    #pragma unroll
    for (int nt = 0; nt < 4; nt++) {
        b1f[nt].x = b1s[nh * 32 + nt * 8 + 2 * qc];
        b1f[nt].y = b1s[nh * 32 + nt * 8 + 2 * qc + 1];
    }
    float* svp = nh ? sv1 : sv0;
    float wmax = -3.4e38f;           // max of this warp's partial scores

    for (int p = wp; p < 72; p += 4) {
        const int t  = p >> 1;
        const int h  = p & 1;
        const int ib = TI_ARR[t] * 8 + 4 * h;
        const int jb = TJ_ARR[t] * 8;
        const uint4* uj4 = (const uint4*)(u16p + (jb + grp) * UHS);
        const uint4* ua4 = (const uint4*)(u16p + ib * UHS);  // +11 per row

        float acc0[4][4], acc1[4][4];
        #pragma unroll
        for (int nt = 0; nt < 4; nt++) {
            acc0[nt][0] = b1f[nt].x; acc0[nt][1] = b1f[nt].y;
            acc0[nt][2] = b1f[nt].x; acc0[nt][3] = b1f[nt].y;
            acc1[nt][0] = b1f[nt].x; acc1[nt][1] = b1f[nt].y;
            acc1[nt][2] = b1f[nt].x; acc1[nt][3] = b1f[nt].y;
        }

        #pragma unroll
        for (int c = 0; c < 2; c++) {
            const int o = 2 * qc + c;
            const uint4 uj = uj4[o];
            const uint4 q0 = ua4[o];
            const uint4 q1 = ua4[o + 11];
            const uint4 q2 = ua4[o + 22];
            const uint4 q3 = ua4[o + 33];
            {
                const uint32_t a0 = hmul2(q0.x, uj.x);
                const uint32_t a1 = hmul2(q1.x, uj.x);
                const uint32_t a2 = hmul2(q0.y, uj.y);
                const uint32_t a3 = hmul2(q1.y, uj.y);
                const uint32_t c0 = hmul2(q2.x, uj.x);
                const uint32_t c1 = hmul2(q3.x, uj.x);
                const uint32_t c2 = hmul2(q2.y, uj.y);
                const uint32_t c3 = hmul2(q3.y, uj.y);
                #pragma unroll
                for (int nt = 0; nt < 4; nt++) {
                    mma16(acc0[nt], a0, a1, a2, a3,
                          Bc[nt][2 * c].x, Bc[nt][2 * c].y);
                    mma16(acc1[nt], c0, c1, c2, c3,
                          Bc[nt][2 * c].x, Bc[nt][2 * c].y);
                }
            }
            {
                const uint32_t a0 = hmul2(q0.z, uj.z);
                const uint32_t a1 = hmul2(q1.z, uj.z);
                const uint32_t a2 = hmul2(q0.w, uj.w);
                const uint32_t a3 = hmul2(q1.w, uj.w);
                const uint32_t c0 = hmul2(q2.z, uj.z);
                const uint32_t c1 = hmul2(q3.z, uj.z);
                const uint32_t c2 = hmul2(q2.w, uj.w);
                const uint32_t c3 = hmul2(q3.w, uj.w);
                #pragma unroll
                for (int nt = 0; nt < 4; nt++) {
                    mma16(acc0[nt], a0, a1, a2, a3,
                          Bc[nt][2 * c + 1].x, Bc[nt][2 * c + 1].y);
                    mma16(acc1[nt], c0, c1, c2, c3,
                          Bc[nt][2 * c + 1].x, Bc[nt][2 * c + 1].y);
                }
            }
        }

        // tensor-core epilogue: s = relu(H) . w2 -- two INDEPENDENT MMAs per
        // score set (separate accumulators), merged with one fp32 add.
        float sA[4] = {0.f, 0.f, 0.f, 0.f};
        float sB[4] = {0.f, 0.f, 0.f, 0.f};
        mma16(sA,
              packh2_relu(acc0[0][0], acc0[0][1]),
              packh2_relu(acc0[0][2], acc0[0][3]),
              packh2_relu(acc0[1][0], acc0[1][1]),
              packh2_relu(acc0[1][2], acc0[1][3]),
              w2f[0][0], w2f[0][1]);
        mma16(sB,
              packh2_relu(acc0[2][0], acc0[2][1]),
              packh2_relu(acc0[2][2], acc0[2][3]),
              packh2_relu(acc0[3][0], acc0[3][1]),
              packh2_relu(acc0[3][2], acc0[3][3]),
              w2f[1][0], w2f[1][1]);
        float sC[4] = {0.f, 0.f, 0.f, 0.f};
        float sD[4] = {0.f, 0.f, 0.f, 0.f};
        mma16(sC,
              packh2_relu(acc1[0][0], acc1[0][1]),
              packh2_relu(acc1[0][2], acc1[0][3]),
              packh2_relu(acc1[1][0], acc1[1][1]),
              packh2_relu(acc1[1][2], acc1[1][3]),
              w2f[0][0], w2f[0][1]);
        mma16(sD,
              packh2_relu(acc1[2][0], acc1[2][1]),
              packh2_relu(acc1[2][2], acc1[2][3]),
              packh2_relu(acc1[3][0], acc1[3][1]),
              packh2_relu(acc1[3][2], acc1[3][3]),
              w2f[1][0], w2f[1][1]);

        const float r0 = sA[0] + sB[0];
        const float r1 = sA[2] + sB[2];
        const float r2 = sC[0] + sD[0];
        const float r3 = sC[2] + sD[2];
        wmax = fmaxf(wmax, fmaxf(fmaxf(r0, r1), fmaxf(r2, r3)));

        if (qc == 0) {
            const int j = jb + grp;
            svp[(ib + 0) * SVS + j] = r0;
            svp[(ib + 1) * SVS + j] = r1;
            svp[(ib + 2) * SVS + j] = r2;
            svp[(ib + 3) * SVS + j] = r3;
        }
    }
    // warp max of partial scores -> redbuf
    #pragma unroll
    for (int d = 16; d; d >>= 1)
        wmax = fmaxf(wmax, __shfl_xor_sync(~0u, wmax, d));
    if (lane == 0) redbuf[wid] = wmax;
    __syncthreads();

    // m = max(0, maxP0 + maxP1) >= true max (valid softmax shift, exact math)
    const float mP0 = fmaxf(fmaxf(redbuf[0], redbuf[2]),
                            fmaxf(redbuf[4], redbuf[6]));
    const float mP1 = fmaxf(fmaxf(redbuf[1], redbuf[3]),
                            fmaxf(redbuf[5], redbuf[7]));
    const float m = fmaxf(0.f, mP0 + mP1);

    // ------------ Pass 2: vectorized masked softmax (float4) -------------
    float le = 0.f;
    #pragma unroll
    for (int it = 0; it < 4; it++) {
        const int lin4 = tid + it * 256;      // float4 index, 0..1023
        const int i  = lin4 >> 4;
        const int j0 = (lin4 & 15) << 2;
        const int sidx = i * SVS + j0;        // 16B aligned (272*i + 16*j4)
        const float4 sa = *(const float4*)(sv0 + sidx);
        const float4 sb = *(const float4*)(sv1 + sidx);
        const float  xi = xb[i];
        const float4 xj = *(const float4*)(xb + j0);
        const bool vi = (xi != 0.f);
        float4 e;
        e.x = (vi && j0 + 0 >= i && xj.x != 0.f) ? __expf(sa.x + sb.x - m) : 0.f;
        e.y = (vi && j0 + 1 >= i && xj.y != 0.f) ? __expf(sa.y + sb.y - m) : 0.f;
        e.z = (vi && j0 + 2 >= i && xj.z != 0.f) ? __expf(sa.z + sb.z - m) : 0.f;
        e.w = (vi && j0 + 3 >= i && xj.w != 0.f) ? __expf(sa.w + sb.w - m) : 0.f;
        e.x = __uint_as_float(to_tf32(e.x));  // exactly what pass 3's MMA sees
        e.y = __uint_as_float(to_tf32(e.y));
        e.z = __uint_as_float(to_tf32(e.z));
        e.w = __uint_as_float(to_tf32(e.w));
        *(float4*)(sv0 + sidx) = e;
        le += (e.x + e.y) + (e.z + e.w);
    }
    #pragma unroll
    for (int d = 16; d; d >>= 1) le += __shfl_xor_sync(~0u, le, d);
    if (lane == 0) redbuf[8 + wid] = le;
    __syncthreads();

    // -------- Pass 3: V = E @ U via tf32 mma; tmp[k] = sum_i u[i,k] V[i,k] --
    {
        const int mt    = wid >> 1;            // 0..3
        const int nbase = (wid & 1) * 4;       // n-tiles nbase..nbase+3

        float vacc[4][4];
        #pragma unroll
        for (int cc = 0; cc < 4; cc++)
            #pragma unroll
            for (int q = 0; q < 4; q++) vacc[cc][q] = 0.f;

        int pkb[4];
        #pragma unroll
        for (int cc = 0; cc < 4; cc++)
            pkb[cc] = posk(8 * (nbase + cc) + grp);

        const float* e0 = sv0 + (16 * mt + grp) * SVS;
        const float* e1 = sv0 + (16 * mt + grp + 8) * SVS;

        #pragma unroll
        for (int js = 0; js < 8; js++) {
            const int jc = 8 * js + qc;
            const uint32_t a0 = __float_as_uint(e0[jc]);
            const uint32_t a1 = __float_as_uint(e1[jc]);
            const uint32_t a2 = __float_as_uint(e0[jc + 4]);
            const uint32_t a3 = __float_as_uint(e1[jc + 4]);
            const float* uj0 = u + jc * US;
            const float* uj1 = u + (jc + 4) * US;
            #pragma unroll
            for (int cc = 0; cc < 4; cc++) {
                const uint32_t b0 = __float_as_uint(uj0[pkb[cc]]);
                const uint32_t b1v = __float_as_uint(uj1[pkb[cc]]);
                mma8(vacc[cc], a0, a1, a2, a3, b0, b1v);
            }
        }

        float part[8];
        #pragma unroll
        for (int cc = 0; cc < 4; cc++) {
            const int k0 = 8 * (nbase + cc) + 2 * qc;
            const int i0 = 16 * mt + grp;
            const float u00 = u[i0 * US + posk(k0)];
            const float u01 = u[i0 * US + posk(k0 + 1)];
            const float u10 = u[(i0 + 8) * US + posk(k0)];
            const float u11 = u[(i0 + 8) * US + posk(k0 + 1)];
            part[2 * cc]     = fmaf(vacc[cc][0], u00, vacc[cc][2] * u10);
            part[2 * cc + 1] = fmaf(vacc[cc][1], u01, vacc[cc][3] * u11);
        }
        #pragma unroll
        for (int d = 4; d <= 16; d <<= 1)
            #pragma unroll
            for (int q = 0; q < 8; q++)
                part[q] += __shfl_xor_sync(0xffffffffu, part[q], d);

        if (grp == 0) {
            #pragma unroll
            for (int cc = 0; cc < 4; cc++) {
                const int k0 = 8 * (nbase + cc) + 2 * qc;
                acc4s[mt][k0]     = part[2 * cc];
                acc4s[mt][k0 + 1] = part[2 * cc + 1];
            }
        }
    }
    __syncthreads();
    if (tid < NK) {
        float denom = __expf(-m);          // seed zeros(1) entry
        #pragma unroll
        for (int w = 0; w < 8; w++) denom += redbuf[8 + w];
        tmpv[tid] = (acc4s[0][tid] + acc4s[1][tid] +
                     acc4s[2][tid] + acc4s[3][tid]) / denom;
    }
    __syncthreads();

    // ---------------- Pass 4: deep MLP on warp 0 (smem weights) ------------
    if (wid == 0) {
        {
            float a = bd1[lane];
            const float4* w4 = (const float4*)(wd1s + lane * 64);
            #pragma unroll 4
            for (int j4 = 0; j4 < 16; j4++) {
                const float4 wv = w4[j4];
                a = fmaf(wv.x, tmpv[4 * j4 + 0], a);
                a = fmaf(wv.y, tmpv[4 * j4 + 1], a);
                a = fmaf(wv.z, tmpv[4 * j4 + 2], a);
                a = fmaf(wv.w, tmpv[4 * j4 + 3], a);
            }
            d1s[lane] = fmaxf(a, 0.f);
        }
        __syncwarp();
        if (lane < 21) {
            float a = bd2[lane];
            const float4* w4 = (const float4*)(wd2s + lane * 32);
            #pragma unroll
            for (int j4 = 0; j4 < 8; j4++) {
                const float4 wv = w4[j4];
                a = fmaf(wv.x, d1s[4 * j4 + 0], a);
                a = fmaf(wv.y, d1s[4 * j4 + 1], a);
                a = fmaf(wv.z, d1s[4 * j4 + 2], a);
                a = fmaf(wv.w, d1s[4 * j4 + 3], a);
            }
            d2s[lane] = fmaxf(a, 0.f);
        }
        __syncwarp();
        if (lane < 16) {
            float a = bd3[lane];
            const float* w = wd3s + lane * 21;
            #pragma unroll
            for (int j = 0; j < 21; j++) a = fmaf(w[j], d2s[j], a);
            d3s[lane] = fmaxf(a, 0.f);
        }
        __syncwarp();
        if (lane == 0) {
            float o = bo[0];
            #pragma unroll
            for (int j = 0; j < 16; j++) o = fmaf(wos[j], d3s[j], o);
            float lin = bw[0];
            #pragma unroll 8
            for (int f = 0; f < NF; f++) lin = fmaf(wws[f], xb[f], lin);
            out[b] = 1.f / (1.f + __expf(-(lin + o)));
        }
    }
}

extern "C" void kernel_launch(void* const* d_in, const int* in_sizes, int n_in,
                              void* d_out, int out_size)
{
    const float* x     = (const float*)d_in[0];
    const float* Ww    = (const float*)d_in[1];
    const float* bw    = (const float*)d_in[2];
    const float* cross = (const float*)d_in[3];
    const float* W1    = (const float*)d_in[4];
    const float* b1    = (const float*)d_in[5];
    const float* w2    = (const float*)d_in[6];
    const float* Wd1   = (const float*)d_in[7];
    const float* bd1   = (const float*)d_in[8];
    const float* Wd2   = (const float*)d_in[9];
    const float* bd2   = (const float*)d_in[10];
    const float* Wd3   = (const float*)d_in[11];
    const float* bd3   = (const float*)d_in[12];
    const float* Wo    = (const float*)d_in[13];
    const float* bo    = (const float*)d_in[14];
    float* out = (float*)d_out;

    const size_t dyn_smem = (size_t)DSM_FLOATS * sizeof(float); // 90,368 B
    cudaFuncSetAttribute(afm_kernel,
                         cudaFuncAttributeMaxDynamicSharedMemorySize,
                         (int)dyn_smem);

    afm_kernel<<<NB, 256, dyn_smem>>>(x, Ww, bw, cross, W1, b1, w2,
                                      Wd1, bd1, Wd2, bd2, Wd3, bd3, Wo, bo,
                                      out);
}